// round 7
// baseline (speedup 1.0000x reference)
#include <cuda_runtime.h>
#include <math.h>
#include <stdint.h>

// Problem constants
#define B_SZ   4
#define S_LEN  1024
#define D_DIM  1024
#define H_N    16
#define DKH    64
#define DF_DIM 4096
#define NROWS  (B_SZ * S_LEN)         // 4096
#define TOPK   307                    // int(1024 * 0.3)

// ---------------------------------------------------------------------------
// Scratch (static device globals; no runtime allocation allowed)
// ---------------------------------------------------------------------------
__device__ float g_h  [NROWS * D_DIM];     // LN output (reused for LN2)
__device__ float g_q  [NROWS * D_DIM];
__device__ float g_k  [NROWS * D_DIM];
__device__ float g_v  [NROWS * D_DIM];
__device__ float g_ctx[NROWS * D_DIM];
__device__ float g_x1 [NROWS * D_DIM];
__device__ float g_f1 [NROWS * DF_DIM];
__device__ float g_f2 [NROWS * DF_DIM];
__device__ float g_attn_fb[B_SZ * H_N * S_LEN * S_LEN];   // fallback if d_out lacks attn

__device__ __forceinline__ float gelu_f(float x) {
    return 0.5f * x * (1.0f + erff(x * 0.70710678118654752440f));
}

// ---------------------------------------------------------------------------
// LayerNorm: one block per row of 1024
// ---------------------------------------------------------------------------
__global__ __launch_bounds__(256) void ln_kernel(const float* __restrict__ x,
                                                 const float* __restrict__ g,
                                                 const float* __restrict__ b,
                                                 float* __restrict__ out) {
    __shared__ float rs[256], rq[256];
    int row = blockIdx.x, tid = threadIdx.x;
    const float4* px = (const float4*)(x + (size_t)row * D_DIM);
    float4 v = px[tid];
    float s = v.x + v.y + v.z + v.w;
    float q = v.x*v.x + v.y*v.y + v.z*v.z + v.w*v.w;
    rs[tid] = s; rq[tid] = q;
    __syncthreads();
    for (int st = 128; st > 0; st >>= 1) {
        if (tid < st) { rs[tid] += rs[tid+st]; rq[tid] += rq[tid+st]; }
        __syncthreads();
    }
    float mu  = rs[0] * (1.0f / D_DIM);
    float var = rq[0] * (1.0f / D_DIM) - mu * mu;
    float rstd = rsqrtf(var + 1e-5f);
    float4 gg = ((const float4*)g)[tid];
    float4 bb = ((const float4*)b)[tid];
    float4 o;
    o.x = (v.x - mu) * rstd * gg.x + bb.x;
    o.y = (v.y - mu) * rstd * gg.y + bb.y;
    o.z = (v.z - mu) * rstd * gg.z + bb.z;
    o.w = (v.w - mu) * rstd * gg.w + bb.w;
    ((float4*)(out + (size_t)row * D_DIM))[tid] = o;
}

// ---------------------------------------------------------------------------
// SGEMM NT: C[m,n] = alpha * sum_k A[m,k]*B[n,k] (+bias[n]) (+epilogue)
// A row-major [M,K] lda, B row-major [N,K] ldb. 128x128x16 tiles, 8x8/thread,
// smem ping-pong double-buffer (1 sync per k-tile).
// MODE: 0 = plain(+bias), 1 = GELU(+bias), 2 = +bias +residual R
// HEAD: batched per-head scores variant (blockIdx.z = b*H + h)
// All dims assumed multiples of tile sizes (true for this problem).
// ---------------------------------------------------------------------------
template<int MODE, bool HEAD>
__global__ __launch_bounds__(256) void sgemm_nt(const float* __restrict__ A,
                                                const float* __restrict__ B,
                                                const float* __restrict__ bias,
                                                const float* __restrict__ R,
                                                float* __restrict__ C,
                                                int K, int lda, int ldb, int ldc,
                                                float alpha, long strideC) {
    __shared__ float As[2][16][132];
    __shared__ float Bs[2][16][132];
    int tid = threadIdx.x;

    const float* Ab = A + (size_t)blockIdx.y * 128 * lda;
    const float* Bb = B + (size_t)blockIdx.x * 128 * ldb;
    float* Cb = C;
    if (HEAD) {
        int z = blockIdx.z;
        size_t off = (size_t)(z >> 4) * (S_LEN * D_DIM) + (size_t)(z & 15) * DKH;
        Ab += off; Bb += off;
        Cb += (size_t)z * strideC;
    }

    int tx = tid & 15, ty = tid >> 4;
    int lr = tid >> 2;            // 0..63
    int lc = (tid & 3) << 2;      // 0,4,8,12

    float acc[8][8];
#pragma unroll
    for (int i = 0; i < 8; i++)
#pragma unroll
        for (int j = 0; j < 8; j++) acc[i][j] = 0.0f;

    // preload first k-tile
#pragma unroll
    for (int r = 0; r < 2; r++) {
        int row = lr + r * 64;
        float4 va = *(const float4*)(Ab + (size_t)row * lda + lc);
        As[0][lc+0][row] = va.x; As[0][lc+1][row] = va.y;
        As[0][lc+2][row] = va.z; As[0][lc+3][row] = va.w;
        float4 vb = *(const float4*)(Bb + (size_t)row * ldb + lc);
        Bs[0][lc+0][row] = vb.x; Bs[0][lc+1][row] = vb.y;
        Bs[0][lc+2][row] = vb.z; Bs[0][lc+3][row] = vb.w;
    }
    __syncthreads();

    int buf = 0;
    for (int k0 = 0; k0 < K; k0 += 16) {
        float4 pa[2], pb[2];
        bool more = (k0 + 16 < K);
        if (more) {
#pragma unroll
            for (int r = 0; r < 2; r++) {
                int row = lr + r * 64;
                pa[r] = *(const float4*)(Ab + (size_t)row * lda + (k0 + 16) + lc);
                pb[r] = *(const float4*)(Bb + (size_t)row * ldb + (k0 + 16) + lc);
            }
        }
#pragma unroll
        for (int k = 0; k < 16; k++) {
            float4 a0 = *(const float4*)(&As[buf][k][ty * 8]);
            float4 a1 = *(const float4*)(&As[buf][k][ty * 8 + 4]);
            float4 b0 = *(const float4*)(&Bs[buf][k][tx * 8]);
            float4 b1 = *(const float4*)(&Bs[buf][k][tx * 8 + 4]);
            float ra[8] = {a0.x, a0.y, a0.z, a0.w, a1.x, a1.y, a1.z, a1.w};
            float rb[8] = {b0.x, b0.y, b0.z, b0.w, b1.x, b1.y, b1.z, b1.w};
#pragma unroll
            for (int i = 0; i < 8; i++)
#pragma unroll
                for (int j = 0; j < 8; j++)
                    acc[i][j] = fmaf(ra[i], rb[j], acc[i][j]);
        }
        if (more) {
            int nb = buf ^ 1;
#pragma unroll
            for (int r = 0; r < 2; r++) {
                int row = lr + r * 64;
                As[nb][lc+0][row] = pa[r].x; As[nb][lc+1][row] = pa[r].y;
                As[nb][lc+2][row] = pa[r].z; As[nb][lc+3][row] = pa[r].w;
                Bs[nb][lc+0][row] = pb[r].x; Bs[nb][lc+1][row] = pb[r].y;
                Bs[nb][lc+2][row] = pb[r].z; Bs[nb][lc+3][row] = pb[r].w;
            }
        }
        __syncthreads();
        buf ^= 1;
    }

#pragma unroll
    for (int i = 0; i < 8; i++) {
        size_t m = (size_t)blockIdx.y * 128 + ty * 8 + i;
#pragma unroll
        for (int j4 = 0; j4 < 8; j4 += 4) {
            int n = blockIdx.x * 128 + tx * 8 + j4;
            float4 v;
            v.x = acc[i][j4+0] * alpha;
            v.y = acc[i][j4+1] * alpha;
            v.z = acc[i][j4+2] * alpha;
            v.w = acc[i][j4+3] * alpha;
            if (bias != nullptr) {
                float4 bb = *(const float4*)(bias + n);
                v.x += bb.x; v.y += bb.y; v.z += bb.z; v.w += bb.w;
            }
            if (MODE == 1) {
                v.x = gelu_f(v.x); v.y = gelu_f(v.y);
                v.z = gelu_f(v.z); v.w = gelu_f(v.w);
            }
            if (MODE == 2) {
                float4 rr = *(const float4*)(R + m * ldc + n);
                v.x += rr.x; v.y += rr.y; v.z += rr.z; v.w += rr.w;
            }
            *(float4*)(Cb + m * ldc + n) = v;
        }
    }
}

// ---------------------------------------------------------------------------
// Exact top-k(307) + softmax per row of 1024, in place.
// Radix select on order-preserving uint keys (4 x 8-bit passes, shared hist +
// parallel suffix scan). Ties at the threshold kept by lowest index
// (matches jax.lax.top_k). Non-kept entries -> 0 (softmax over -inf canvas).
// ---------------------------------------------------------------------------
__global__ __launch_bounds__(256) void topk_softmax_kernel(float* __restrict__ attn) {
    __shared__ float vals[1024];
    __shared__ unsigned int keys[1024];
    __shared__ unsigned int hist[256];
    __shared__ unsigned int sufs[256];
    __shared__ int tie_idx[1024];
    __shared__ unsigned char keep[1024];
    __shared__ float red[256];
    __shared__ int s_bsel, s_rsub, s_tcnt;

    int tid = threadIdx.x;
    float* p = attn + (size_t)blockIdx.x * 1024;

    for (int i = tid; i < 1024; i += 256) {
        float v = p[i];
        vals[i] = v;
        unsigned u = __float_as_uint(v);
        keys[i] = (u & 0x80000000u) ? ~u : (u | 0x80000000u);
    }
    __syncthreads();

    unsigned prefix = 0u, pmask = 0u;
    int r = TOPK;
    for (int shift = 24; shift >= 0; shift -= 8) {
        hist[tid] = 0u;
        __syncthreads();
        for (int i = tid; i < 1024; i += 256) {
            unsigned kk = keys[i];
            if ((kk & pmask) == prefix) atomicAdd(&hist[(kk >> shift) & 0xFFu], 1u);
        }
        __syncthreads();
        unsigned xv = hist[tid];
        sufs[tid] = xv;
        __syncthreads();
#pragma unroll
        for (int d = 1; d < 256; d <<= 1) {
            unsigned t = (tid + d < 256) ? sufs[tid + d] : 0u;
            __syncthreads();
            sufs[tid] += t;
            __syncthreads();
        }
        // sufs[b] = count of candidates with byte >= b
        unsigned cum  = sufs[tid];
        unsigned cumn = (tid < 255) ? sufs[tid + 1] : 0u;
        if ((int)cum >= r && (int)cumn < r) { s_bsel = tid; s_rsub = (int)cumn; }
        __syncthreads();
        prefix |= ((unsigned)s_bsel) << shift;
        pmask  |= (0xFFu << shift);
        r -= s_rsub;
        __syncthreads();
    }
    unsigned tk = prefix;   // exact k-th largest key; r ties must be kept

    if (tid == 0) s_tcnt = 0;
    __syncthreads();
    for (int i = tid; i < 1024; i += 256) {
        unsigned kk = keys[i];
        unsigned char kp = (kk > tk) ? (unsigned char)1 : (unsigned char)0;
        if (kk == tk) { int pos = atomicAdd(&s_tcnt, 1); tie_idx[pos] = i; }
        keep[i] = kp;
    }
    __syncthreads();
    int tc = s_tcnt;
    for (int j = tid; j < tc; j += 256) {
        int myi = tie_idx[j];
        int rank = 0;
        for (int l = 0; l < tc; l++) rank += (tie_idx[l] < myi) ? 1 : 0;
        if (rank < r) keep[myi] = 1;
    }
    __syncthreads();

    float lm = -3.4e38f;
    for (int i = tid; i < 1024; i += 256)
        if (keep[i]) lm = fmaxf(lm, vals[i]);
    red[tid] = lm;
    __syncthreads();
    for (int st = 128; st > 0; st >>= 1) {
        if (tid < st) red[tid] = fmaxf(red[tid], red[tid + st]);
        __syncthreads();
    }
    float mx = red[0];
    __syncthreads();

    float ls = 0.0f;
    for (int i = tid; i < 1024; i += 256) {
        float e = keep[i] ? expf(vals[i] - mx) : 0.0f;
        vals[i] = e;
        ls += e;
    }
    red[tid] = ls;
    __syncthreads();
    for (int st = 128; st > 0; st >>= 1) {
        if (tid < st) red[tid] += red[tid + st];
        __syncthreads();
    }
    float inv = 1.0f / red[0];
    __syncthreads();
    for (int i = tid; i < 1024; i += 256) p[i] = vals[i] * inv;
}

// ---------------------------------------------------------------------------
// ctx = attn @ V per head. attn [B*H, S, S]; V [B,S,H*DK] row-major.
// Output ctx as [B, S, H*DK] (ready for Wo projection).
// Block: 128 q-rows x 64 dk cols; grid (S/128, B*H).
// ---------------------------------------------------------------------------
__global__ __launch_bounds__(256) void attn_v_kernel(const float* __restrict__ attn,
                                                     const float* __restrict__ V,
                                                     float* __restrict__ ctx) {
    __shared__ float As[128][33];
    __shared__ float Bs[32][68];
    int tid = threadIdx.x;
    int z = blockIdx.y;
    int b = z >> 4, h = z & 15;
    const float* Ab = attn + (size_t)z * (S_LEN * S_LEN) + (size_t)blockIdx.x * 128 * S_LEN;
    const float* Vb = V + (size_t)b * (S_LEN * D_DIM) + h * DKH;
    int tx = tid & 15, ty = tid >> 4;

    float acc[8][4];
#pragma unroll
    for (int i = 0; i < 8; i++)
#pragma unroll
        for (int j = 0; j < 4; j++) acc[i][j] = 0.0f;

    for (int k0 = 0; k0 < S_LEN; k0 += 32) {
#pragma unroll
        for (int r2 = 0; r2 < 4; r2++) {
            int row = r2 * 32 + (tid >> 3);
            int c4 = (tid & 7) << 2;
            float4 v = *(const float4*)(Ab + (size_t)row * S_LEN + k0 + c4);
            As[row][c4+0] = v.x; As[row][c4+1] = v.y;
            As[row][c4+2] = v.z; As[row][c4+3] = v.w;
        }
#pragma unroll
        for (int r2 = 0; r2 < 2; r2++) {
            int row = r2 * 16 + (tid >> 4);
            int c4 = (tid & 15) << 2;
            float4 v = *(const float4*)(Vb + (size_t)(k0 + row) * D_DIM + c4);
            Bs[row][c4+0] = v.x; Bs[row][c4+1] = v.y;
            Bs[row][c4+2] = v.z; Bs[row][c4+3] = v.w;
        }
        __syncthreads();
#pragma unroll
        for (int k = 0; k < 32; k++) {
            float ra[8];
#pragma unroll
            for (int i = 0; i < 8; i++) ra[i] = As[ty * 8 + i][k];
            float rb0 = Bs[k][tx*4+0], rb1 = Bs[k][tx*4+1];
            float rb2 = Bs[k][tx*4+2], rb3 = Bs[k][tx*4+3];
#pragma unroll
            for (int i = 0; i < 8; i++) {
                acc[i][0] = fmaf(ra[i], rb0, acc[i][0]);
                acc[i][1] = fmaf(ra[i], rb1, acc[i][1]);
                acc[i][2] = fmaf(ra[i], rb2, acc[i][2]);
                acc[i][3] = fmaf(ra[i], rb3, acc[i][3]);
            }
        }
        __syncthreads();
    }
#pragma unroll
    for (int i = 0; i < 8; i++) {
        size_t row = (size_t)b * S_LEN + (size_t)blockIdx.x * 128 + ty * 8 + i;
        float4 v;
        v.x = acc[i][0]; v.y = acc[i][1]; v.z = acc[i][2]; v.w = acc[i][3];
        *(float4*)(ctx + row * D_DIM + h * DKH + tx * 4) = v;
    }
}

// ---------------------------------------------------------------------------
// Launch
// ---------------------------------------------------------------------------
extern "C" void kernel_launch(void* const* d_in, const int* in_sizes, int n_in,
                              void* d_out, int out_size) {
    const float* x   = (const float*)d_in[0];
    const float* Wq  = (const float*)d_in[1];
    const float* bq  = (const float*)d_in[2];
    const float* Wk  = (const float*)d_in[3];
    const float* bk  = (const float*)d_in[4];
    const float* Wv  = (const float*)d_in[5];
    const float* bv  = (const float*)d_in[6];
    const float* Wo  = (const float*)d_in[7];
    const float* bo  = (const float*)d_in[8];
    const float* W1  = (const float*)d_in[9];
    const float* b1  = (const float*)d_in[10];
    const float* Wm  = (const float*)d_in[11];
    const float* bm  = (const float*)d_in[12];
    const float* W2  = (const float*)d_in[13];
    const float* b2  = (const float*)d_in[14];
    const float* g1  = (const float*)d_in[15];
    const float* be1 = (const float*)d_in[16];
    const float* g2  = (const float*)d_in[17];
    const float* be2 = (const float*)d_in[18];

    // Resolve device-global scratch addresses once (correctness run precedes
    // graph capture, so no runtime API is called during capture).
    static float *ph = nullptr, *pq, *pk, *pv, *pctx, *px1, *pf1, *pf2, *pfb;
    if (ph == nullptr) {
        cudaGetSymbolAddress((void**)&ph,   g_h);
        cudaGetSymbolAddress((void**)&pq,   g_q);
        cudaGetSymbolAddress((void**)&pk,   g_k);
        cudaGetSymbolAddress((void**)&pv,   g_v);
        cudaGetSymbolAddress((void**)&pctx, g_ctx);
        cudaGetSymbolAddress((void**)&px1,  g_x1);
        cudaGetSymbolAddress((void**)&pf1,  g_f1);
        cudaGetSymbolAddress((void**)&pf2,  g_f2);
        cudaGetSymbolAddress((void**)&pfb,  g_attn_fb);
    }

    float* out_x = (float*)d_out;
    long long attn_elems = (long long)B_SZ * H_N * S_LEN * S_LEN;     // 67,108,864
    long long x_elems = (long long)NROWS * D_DIM;                     // 4,194,304
    float* attn = ((long long)out_size >= x_elems + attn_elems)
                      ? (out_x + x_elems) : pfb;

    // 1. h = LN(x; g1, be1)
    ln_kernel<<<NROWS, 256>>>(x, g1, be1, ph);

    // 2. Q, K, V = h @ W{q,k,v}^T + b   ([B*S, D] layout == [B,S,H,DK])
    dim3 gQKV(D_DIM / 128, NROWS / 128, 1);
    sgemm_nt<0, false><<<gQKV, 256>>>(ph, Wq, bq, nullptr, pq, D_DIM, D_DIM, D_DIM, D_DIM, 1.0f, 0);
    sgemm_nt<0, false><<<gQKV, 256>>>(ph, Wk, bk, nullptr, pk, D_DIM, D_DIM, D_DIM, D_DIM, 1.0f, 0);
    sgemm_nt<0, false><<<gQKV, 256>>>(ph, Wv, bv, nullptr, pv, D_DIM, D_DIM, D_DIM, D_DIM, 1.0f, 0);

    // 3. scores[b,h] = Q_bh @ K_bh^T / 8  -> written directly into attn region
    dim3 gS(S_LEN / 128, S_LEN / 128, B_SZ * H_N);
    sgemm_nt<0, true><<<gS, 256>>>(pq, pk, nullptr, nullptr, attn,
                                   DKH, D_DIM, D_DIM, S_LEN, 0.125f,
                                   (long)S_LEN * S_LEN);

    // 4. top-k(307) + softmax, in place
    topk_softmax_kernel<<<B_SZ * H_N * S_LEN, 256>>>(attn);

    // 5. ctx = attn @ V   ([B,S,H*DK])
    attn_v_kernel<<<dim3(S_LEN / 128, B_SZ * H_N), 256>>>(attn, pv, pctx);

    // 6. x1 = x + ctx @ Wo^T + bo
    sgemm_nt<2, false><<<dim3(D_DIM / 128, NROWS / 128), 256>>>(
        pctx, Wo, bo, x, px1, D_DIM, D_DIM, D_DIM, D_DIM, 1.0f, 0);

    // 7. h2 = LN(x1; g2, be2)
    ln_kernel<<<NROWS, 256>>>(px1, g2, be2, ph);

    // 8. f1 = gelu(h2 @ W1^T + b1)
    sgemm_nt<1, false><<<dim3(DF_DIM / 128, NROWS / 128), 256>>>(
        ph, W1, b1, nullptr, pf1, D_DIM, D_DIM, D_DIM, DF_DIM, 1.0f, 0);

    // 9. f2 = gelu(f1 @ Wm^T + bm)
    sgemm_nt<1, false><<<dim3(DF_DIM / 128, NROWS / 128), 256>>>(
        pf1, Wm, bm, nullptr, pf2, DF_DIM, DF_DIM, DF_DIM, DF_DIM, 1.0f, 0);

    // 10. out_x = x1 + f2 @ W2^T + b2
    sgemm_nt<2, false><<<dim3(D_DIM / 128, NROWS / 128), 256>>>(
        pf2, W2, b2, px1, out_x, DF_DIM, DF_DIM, DF_DIM, D_DIM, 1.0f, 0);
}

// round 8
// speedup vs baseline: 1.0029x; 1.0029x over previous
#include <cuda_runtime.h>
#include <math.h>
#include <stdint.h>

// Problem constants
#define B_SZ   4
#define S_LEN  1024
#define D_DIM  1024
#define H_N    16
#define DKH    64
#define DF_DIM 4096
#define NROWS  (B_SZ * S_LEN)         // 4096
#define TOPK   307                    // int(1024 * 0.3)

// ---------------------------------------------------------------------------
// Scratch (static device globals; no runtime allocation allowed)
// ---------------------------------------------------------------------------
__device__ float g_h  [NROWS * D_DIM];     // LN output (reused for LN2)
__device__ float g_q  [NROWS * D_DIM];
__device__ float g_k  [NROWS * D_DIM];
__device__ float g_v  [NROWS * D_DIM];
__device__ float g_ctx[NROWS * D_DIM];
__device__ float g_x1 [NROWS * D_DIM];
__device__ float g_f1 [NROWS * DF_DIM];
__device__ float g_f2 [NROWS * DF_DIM];
__device__ float g_attn_fb[B_SZ * H_N * S_LEN * S_LEN];   // fallback if d_out lacks attn

__device__ __forceinline__ float gelu_f(float x) {
    return 0.5f * x * (1.0f + erff(x * 0.70710678118654752440f));
}

// ---------------------------------------------------------------------------
// LayerNorm: one block per row of 1024
// ---------------------------------------------------------------------------
__global__ __launch_bounds__(256) void ln_kernel(const float* __restrict__ x,
                                                 const float* __restrict__ g,
                                                 const float* __restrict__ b,
                                                 float* __restrict__ out) {
    __shared__ float rs[256], rq[256];
    int row = blockIdx.x, tid = threadIdx.x;
    const float4* px = (const float4*)(x + (size_t)row * D_DIM);
    float4 v = px[tid];
    float s = v.x + v.y + v.z + v.w;
    float q = v.x*v.x + v.y*v.y + v.z*v.z + v.w*v.w;
    rs[tid] = s; rq[tid] = q;
    __syncthreads();
    for (int st = 128; st > 0; st >>= 1) {
        if (tid < st) { rs[tid] += rs[tid+st]; rq[tid] += rq[tid+st]; }
        __syncthreads();
    }
    float mu  = rs[0] * (1.0f / D_DIM);
    float var = rq[0] * (1.0f / D_DIM) - mu * mu;
    float rstd = rsqrtf(var + 1e-5f);
    float4 gg = ((const float4*)g)[tid];
    float4 bb = ((const float4*)b)[tid];
    float4 o;
    o.x = (v.x - mu) * rstd * gg.x + bb.x;
    o.y = (v.y - mu) * rstd * gg.y + bb.y;
    o.z = (v.z - mu) * rstd * gg.z + bb.z;
    o.w = (v.w - mu) * rstd * gg.w + bb.w;
    ((float4*)(out + (size_t)row * D_DIM))[tid] = o;
}

// ---------------------------------------------------------------------------
// SGEMM NT: C[m,n] = alpha * sum_k A[m,k]*B[n,k] (+bias[n]) (+epilogue)
// A row-major [M,K] lda, B row-major [N,K] ldb. 128x128x16 tiles, 8x8/thread,
// smem ping-pong double-buffer (1 sync per k-tile).
// MODE: 0 = plain(+bias), 1 = GELU(+bias), 2 = +bias +residual R
// HEAD: batched per-head scores variant (blockIdx.z = b*H + h)
// All dims assumed multiples of tile sizes (true for this problem).
// ---------------------------------------------------------------------------
template<int MODE, bool HEAD>
__global__ __launch_bounds__(256) void sgemm_nt(const float* __restrict__ A,
                                                const float* __restrict__ B,
                                                const float* __restrict__ bias,
                                                const float* __restrict__ R,
                                                float* __restrict__ C,
                                                int K, int lda, int ldb, int ldc,
                                                float alpha, long strideC) {
    __shared__ float As[2][16][132];
    __shared__ float Bs[2][16][132];
    int tid = threadIdx.x;

    const float* Ab = A + (size_t)blockIdx.y * 128 * lda;
    const float* Bb = B + (size_t)blockIdx.x * 128 * ldb;
    float* Cb = C;
    if (HEAD) {
        int z = blockIdx.z;
        size_t off = (size_t)(z >> 4) * (S_LEN * D_DIM) + (size_t)(z & 15) * DKH;
        Ab += off; Bb += off;
        Cb += (size_t)z * strideC;
    }

    int tx = tid & 15, ty = tid >> 4;
    int lr = tid >> 2;            // 0..63
    int lc = (tid & 3) << 2;      // 0,4,8,12

    float acc[8][8];
#pragma unroll
    for (int i = 0; i < 8; i++)
#pragma unroll
        for (int j = 0; j < 8; j++) acc[i][j] = 0.0f;

    // preload first k-tile
#pragma unroll
    for (int r = 0; r < 2; r++) {
        int row = lr + r * 64;
        float4 va = *(const float4*)(Ab + (size_t)row * lda + lc);
        As[0][lc+0][row] = va.x; As[0][lc+1][row] = va.y;
        As[0][lc+2][row] = va.z; As[0][lc+3][row] = va.w;
        float4 vb = *(const float4*)(Bb + (size_t)row * ldb + lc);
        Bs[0][lc+0][row] = vb.x; Bs[0][lc+1][row] = vb.y;
        Bs[0][lc+2][row] = vb.z; Bs[0][lc+3][row] = vb.w;
    }
    __syncthreads();

    int buf = 0;
    for (int k0 = 0; k0 < K; k0 += 16) {
        float4 pa[2], pb[2];
        bool more = (k0 + 16 < K);
        if (more) {
#pragma unroll
            for (int r = 0; r < 2; r++) {
                int row = lr + r * 64;
                pa[r] = *(const float4*)(Ab + (size_t)row * lda + (k0 + 16) + lc);
                pb[r] = *(const float4*)(Bb + (size_t)row * ldb + (k0 + 16) + lc);
            }
        }
#pragma unroll
        for (int k = 0; k < 16; k++) {
            float4 a0 = *(const float4*)(&As[buf][k][ty * 8]);
            float4 a1 = *(const float4*)(&As[buf][k][ty * 8 + 4]);
            float4 b0 = *(const float4*)(&Bs[buf][k][tx * 8]);
            float4 b1 = *(const float4*)(&Bs[buf][k][tx * 8 + 4]);
            float ra[8] = {a0.x, a0.y, a0.z, a0.w, a1.x, a1.y, a1.z, a1.w};
            float rb[8] = {b0.x, b0.y, b0.z, b0.w, b1.x, b1.y, b1.z, b1.w};
#pragma unroll
            for (int i = 0; i < 8; i++)
#pragma unroll
                for (int j = 0; j < 8; j++)
                    acc[i][j] = fmaf(ra[i], rb[j], acc[i][j]);
        }
        if (more) {
            int nb = buf ^ 1;
#pragma unroll
            for (int r = 0; r < 2; r++) {
                int row = lr + r * 64;
                As[nb][lc+0][row] = pa[r].x; As[nb][lc+1][row] = pa[r].y;
                As[nb][lc+2][row] = pa[r].z; As[nb][lc+3][row] = pa[r].w;
                Bs[nb][lc+0][row] = pb[r].x; Bs[nb][lc+1][row] = pb[r].y;
                Bs[nb][lc+2][row] = pb[r].z; Bs[nb][lc+3][row] = pb[r].w;
            }
        }
        __syncthreads();
        buf ^= 1;
    }

#pragma unroll
    for (int i = 0; i < 8; i++) {
        size_t m = (size_t)blockIdx.y * 128 + ty * 8 + i;
#pragma unroll
        for (int j4 = 0; j4 < 8; j4 += 4) {
            int n = blockIdx.x * 128 + tx * 8 + j4;
            float4 v;
            v.x = acc[i][j4+0] * alpha;
            v.y = acc[i][j4+1] * alpha;
            v.z = acc[i][j4+2] * alpha;
            v.w = acc[i][j4+3] * alpha;
            if (bias != nullptr) {
                float4 bb = *(const float4*)(bias + n);
                v.x += bb.x; v.y += bb.y; v.z += bb.z; v.w += bb.w;
            }
            if (MODE == 1) {
                v.x = gelu_f(v.x); v.y = gelu_f(v.y);
                v.z = gelu_f(v.z); v.w = gelu_f(v.w);
            }
            if (MODE == 2) {
                float4 rr = *(const float4*)(R + m * ldc + n);
                v.x += rr.x; v.y += rr.y; v.z += rr.z; v.w += rr.w;
            }
            *(float4*)(Cb + m * ldc + n) = v;
        }
    }
}

// ---------------------------------------------------------------------------
// Exact top-k(307) + softmax per row of 1024, in place.
// Radix select on order-preserving uint keys (4 x 8-bit passes, shared hist +
// parallel suffix scan). Ties at the threshold kept by lowest index
// (matches jax.lax.top_k). Non-kept entries -> 0 (softmax over -inf canvas).
// ---------------------------------------------------------------------------
__global__ __launch_bounds__(256) void topk_softmax_kernel(float* __restrict__ attn) {
    __shared__ float vals[1024];
    __shared__ unsigned int keys[1024];
    __shared__ unsigned int hist[256];
    __shared__ unsigned int sufs[256];
    __shared__ int tie_idx[1024];
    __shared__ unsigned char keep[1024];
    __shared__ float red[256];
    __shared__ int s_bsel, s_rsub, s_tcnt;

    int tid = threadIdx.x;
    float* p = attn + (size_t)blockIdx.x * 1024;

    for (int i = tid; i < 1024; i += 256) {
        float v = p[i];
        vals[i] = v;
        unsigned u = __float_as_uint(v);
        keys[i] = (u & 0x80000000u) ? ~u : (u | 0x80000000u);
    }
    __syncthreads();

    unsigned prefix = 0u, pmask = 0u;
    int r = TOPK;
    for (int shift = 24; shift >= 0; shift -= 8) {
        hist[tid] = 0u;
        __syncthreads();
        for (int i = tid; i < 1024; i += 256) {
            unsigned kk = keys[i];
            if ((kk & pmask) == prefix) atomicAdd(&hist[(kk >> shift) & 0xFFu], 1u);
        }
        __syncthreads();
        unsigned xv = hist[tid];
        sufs[tid] = xv;
        __syncthreads();
#pragma unroll
        for (int d = 1; d < 256; d <<= 1) {
            unsigned t = (tid + d < 256) ? sufs[tid + d] : 0u;
            __syncthreads();
            sufs[tid] += t;
            __syncthreads();
        }
        // sufs[b] = count of candidates with byte >= b
        unsigned cum  = sufs[tid];
        unsigned cumn = (tid < 255) ? sufs[tid + 1] : 0u;
        if ((int)cum >= r && (int)cumn < r) { s_bsel = tid; s_rsub = (int)cumn; }
        __syncthreads();
        prefix |= ((unsigned)s_bsel) << shift;
        pmask  |= (0xFFu << shift);
        r -= s_rsub;
        __syncthreads();
    }
    unsigned tk = prefix;   // exact k-th largest key; r ties must be kept

    if (tid == 0) s_tcnt = 0;
    __syncthreads();
    for (int i = tid; i < 1024; i += 256) {
        unsigned kk = keys[i];
        unsigned char kp = (kk > tk) ? (unsigned char)1 : (unsigned char)0;
        if (kk == tk) { int pos = atomicAdd(&s_tcnt, 1); tie_idx[pos] = i; }
        keep[i] = kp;
    }
    __syncthreads();
    int tc = s_tcnt;
    for (int j = tid; j < tc; j += 256) {
        int myi = tie_idx[j];
        int rank = 0;
        for (int l = 0; l < tc; l++) rank += (tie_idx[l] < myi) ? 1 : 0;
        if (rank < r) keep[myi] = 1;
    }
    __syncthreads();

    float lm = -3.4e38f;
    for (int i = tid; i < 1024; i += 256)
        if (keep[i]) lm = fmaxf(lm, vals[i]);
    red[tid] = lm;
    __syncthreads();
    for (int st = 128; st > 0; st >>= 1) {
        if (tid < st) red[tid] = fmaxf(red[tid], red[tid + st]);
        __syncthreads();
    }
    float mx = red[0];
    __syncthreads();

    float ls = 0.0f;
    for (int i = tid; i < 1024; i += 256) {
        float e = keep[i] ? expf(vals[i] - mx) : 0.0f;
        vals[i] = e;
        ls += e;
    }
    red[tid] = ls;
    __syncthreads();
    for (int st = 128; st > 0; st >>= 1) {
        if (tid < st) red[tid] += red[tid + st];
        __syncthreads();
    }
    float inv = 1.0f / red[0];
    __syncthreads();
    for (int i = tid; i < 1024; i += 256) p[i] = vals[i] * inv;
}

// ---------------------------------------------------------------------------
// ctx = attn @ V per head. attn [B*H, S, S]; V [B,S,H*DK] row-major.
// Output ctx as [B, S, H*DK] (ready for Wo projection).
// Block: 128 q-rows x 64 dk cols; grid (S/128, B*H).
// ---------------------------------------------------------------------------
__global__ __launch_bounds__(256) void attn_v_kernel(const float* __restrict__ attn,
                                                     const float* __restrict__ V,
                                                     float* __restrict__ ctx) {
    __shared__ float As[128][33];
    __shared__ float Bs[32][68];
    int tid = threadIdx.x;
    int z = blockIdx.y;
    int b = z >> 4, h = z & 15;
    const float* Ab = attn + (size_t)z * (S_LEN * S_LEN) + (size_t)blockIdx.x * 128 * S_LEN;
    const float* Vb = V + (size_t)b * (S_LEN * D_DIM) + h * DKH;
    int tx = tid & 15, ty = tid >> 4;

    float acc[8][4];
#pragma unroll
    for (int i = 0; i < 8; i++)
#pragma unroll
        for (int j = 0; j < 4; j++) acc[i][j] = 0.0f;

    for (int k0 = 0; k0 < S_LEN; k0 += 32) {
#pragma unroll
        for (int r2 = 0; r2 < 4; r2++) {
            int row = r2 * 32 + (tid >> 3);
            int c4 = (tid & 7) << 2;
            float4 v = *(const float4*)(Ab + (size_t)row * S_LEN + k0 + c4);
            As[row][c4+0] = v.x; As[row][c4+1] = v.y;
            As[row][c4+2] = v.z; As[row][c4+3] = v.w;
        }
#pragma unroll
        for (int r2 = 0; r2 < 2; r2++) {
            int row = r2 * 16 + (tid >> 4);
            int c4 = (tid & 15) << 2;
            float4 v = *(const float4*)(Vb + (size_t)(k0 + row) * D_DIM + c4);
            Bs[row][c4+0] = v.x; Bs[row][c4+1] = v.y;
            Bs[row][c4+2] = v.z; Bs[row][c4+3] = v.w;
        }
        __syncthreads();
#pragma unroll
        for (int k = 0; k < 32; k++) {
            float ra[8];
#pragma unroll
            for (int i = 0; i < 8; i++) ra[i] = As[ty * 8 + i][k];
            float rb0 = Bs[k][tx*4+0], rb1 = Bs[k][tx*4+1];
            float rb2 = Bs[k][tx*4+2], rb3 = Bs[k][tx*4+3];
#pragma unroll
            for (int i = 0; i < 8; i++) {
                acc[i][0] = fmaf(ra[i], rb0, acc[i][0]);
                acc[i][1] = fmaf(ra[i], rb1, acc[i][1]);
                acc[i][2] = fmaf(ra[i], rb2, acc[i][2]);
                acc[i][3] = fmaf(ra[i], rb3, acc[i][3]);
            }
        }
        __syncthreads();
    }
#pragma unroll
    for (int i = 0; i < 8; i++) {
        size_t row = (size_t)b * S_LEN + (size_t)blockIdx.x * 128 + ty * 8 + i;
        float4 v;
        v.x = acc[i][0]; v.y = acc[i][1]; v.z = acc[i][2]; v.w = acc[i][3];
        *(float4*)(ctx + row * D_DIM + h * DKH + tx * 4) = v;
    }
}

// ---------------------------------------------------------------------------
// Launch
// ---------------------------------------------------------------------------
extern "C" void kernel_launch(void* const* d_in, const int* in_sizes, int n_in,
                              void* d_out, int out_size) {
    const float* x   = (const float*)d_in[0];
    const float* Wq  = (const float*)d_in[1];
    const float* bq  = (const float*)d_in[2];
    const float* Wk  = (const float*)d_in[3];
    const float* bk  = (const float*)d_in[4];
    const float* Wv  = (const float*)d_in[5];
    const float* bv  = (const float*)d_in[6];
    const float* Wo  = (const float*)d_in[7];
    const float* bo  = (const float*)d_in[8];
    const float* W1  = (const float*)d_in[9];
    const float* b1  = (const float*)d_in[10];
    const float* Wm  = (const float*)d_in[11];
    const float* bm  = (const float*)d_in[12];
    const float* W2  = (const float*)d_in[13];
    const float* b2  = (const float*)d_in[14];
    const float* g1  = (const float*)d_in[15];
    const float* be1 = (const float*)d_in[16];
    const float* g2  = (const float*)d_in[17];
    const float* be2 = (const float*)d_in[18];

    // Resolve device-global scratch addresses once (correctness run precedes
    // graph capture, so no runtime API is called during capture).
    static float *ph = nullptr, *pq, *pk, *pv, *pctx, *px1, *pf1, *pf2, *pfb;
    if (ph == nullptr) {
        cudaGetSymbolAddress((void**)&ph,   g_h);
        cudaGetSymbolAddress((void**)&pq,   g_q);
        cudaGetSymbolAddress((void**)&pk,   g_k);
        cudaGetSymbolAddress((void**)&pv,   g_v);
        cudaGetSymbolAddress((void**)&pctx, g_ctx);
        cudaGetSymbolAddress((void**)&px1,  g_x1);
        cudaGetSymbolAddress((void**)&pf1,  g_f1);
        cudaGetSymbolAddress((void**)&pf2,  g_f2);
        cudaGetSymbolAddress((void**)&pfb,  g_attn_fb);
    }

    float* out_x = (float*)d_out;
    long long attn_elems = (long long)B_SZ * H_N * S_LEN * S_LEN;     // 67,108,864
    long long x_elems = (long long)NROWS * D_DIM;                     // 4,194,304
    float* attn = ((long long)out_size >= x_elems + attn_elems)
                      ? (out_x + x_elems) : pfb;

    // 1. h = LN(x; g1, be1)
    ln_kernel<<<NROWS, 256>>>(x, g1, be1, ph);

    // 2. Q, K, V = h @ W{q,k,v}^T + b   ([B*S, D] layout == [B,S,H,DK])
    dim3 gQKV(D_DIM / 128, NROWS / 128, 1);
    sgemm_nt<0, false><<<gQKV, 256>>>(ph, Wq, bq, nullptr, pq, D_DIM, D_DIM, D_DIM, D_DIM, 1.0f, 0);
    sgemm_nt<0, false><<<gQKV, 256>>>(ph, Wk, bk, nullptr, pk, D_DIM, D_DIM, D_DIM, D_DIM, 1.0f, 0);
    sgemm_nt<0, false><<<gQKV, 256>>>(ph, Wv, bv, nullptr, pv, D_DIM, D_DIM, D_DIM, D_DIM, 1.0f, 0);

    // 3. scores[b,h] = Q_bh @ K_bh^T / 8  -> written directly into attn region
    dim3 gS(S_LEN / 128, S_LEN / 128, B_SZ * H_N);
    sgemm_nt<0, true><<<gS, 256>>>(pq, pk, nullptr, nullptr, attn,
                                   DKH, D_DIM, D_DIM, S_LEN, 0.125f,
                                   (long)S_LEN * S_LEN);

    // 4. top-k(307) + softmax, in place
    topk_softmax_kernel<<<B_SZ * H_N * S_LEN, 256>>>(attn);

    // 5. ctx = attn @ V   ([B,S,H*DK])
    attn_v_kernel<<<dim3(S_LEN / 128, B_SZ * H_N), 256>>>(attn, pv, pctx);

    // 6. x1 = x + ctx @ Wo^T + bo
    sgemm_nt<2, false><<<dim3(D_DIM / 128, NROWS / 128), 256>>>(
        pctx, Wo, bo, x, px1, D_DIM, D_DIM, D_DIM, D_DIM, 1.0f, 0);

    // 7. h2 = LN(x1; g2, be2)
    ln_kernel<<<NROWS, 256>>>(px1, g2, be2, ph);

    // 8. f1 = gelu(h2 @ W1^T + b1)
    sgemm_nt<1, false><<<dim3(DF_DIM / 128, NROWS / 128), 256>>>(
        ph, W1, b1, nullptr, pf1, D_DIM, D_DIM, D_DIM, DF_DIM, 1.0f, 0);

    // 9. f2 = gelu(f1 @ Wm^T + bm)
    sgemm_nt<1, false><<<dim3(DF_DIM / 128, NROWS / 128), 256>>>(
        pf1, Wm, bm, nullptr, pf2, DF_DIM, DF_DIM, DF_DIM, DF_DIM, 1.0f, 0);

    // 10. out_x = x1 + f2 @ W2^T + b2
    sgemm_nt<2, false><<<dim3(D_DIM / 128, NROWS / 128), 256>>>(
        pf2, W2, b2, px1, out_x, DF_DIM, DF_DIM, DF_DIM, D_DIM, 1.0f, 0);
}